// round 6
// baseline (speedup 1.0000x reference)
#include <cuda_runtime.h>

#define Sv    512
#define Iv    32
#define Hv    128
#define Gv    512      // 4*H
#define NB    8        // batches per CTA
#define NT    256      // threads per CTA (one gate-pair per thread)
#define NCTA  64       // 64 * 8 = 512 batches
#define KRv   64       // h rows 64..127 in registers (both enc and dec)
#define KSe   64       // enc h rows 0..63 in smem (plus 32 x rows)
#define KSd   64       // dec h rows 0..63 in smem

typedef unsigned long long ull;

static __device__ __forceinline__ ull pack2(float a, float b){
    ull r; asm("mov.b64 %0, {%1,%2};" : "=l"(r) : "f"(a), "f"(b)); return r;
}
static __device__ __forceinline__ ull dup2(float a){
    ull r; asm("mov.b64 %0, {%1,%1};" : "=l"(r) : "f"(a)); return r;
}
static __device__ __forceinline__ void unpack2(ull v, float& a, float& b){
    asm("mov.b64 {%0,%1}, %2;" : "=f"(a), "=f"(b) : "l"(v));
}
// Blackwell packed fp32x2 FMA: d = a*b + d (two independent fp32 lanes)
static __device__ __forceinline__ void ffma2(ull& d, ull a, ull b){
    asm("fma.rn.f32x2 %0, %1, %2, %0;" : "+l"(d) : "l"(a), "l"(b));
}
static __device__ __forceinline__ float sig_(float x){
    return __fdividef(1.f, 1.f + __expf(-x));
}
static __device__ __forceinline__ float tanh_(float x){
    float ax = fabsf(x);
    float t  = __expf(-2.f * ax);
    float r  = __fdividef(1.f - t, 1.f + t);
    return copysignf(r, x);
}

// ---- shared memory byte offsets (total 226304 <= 232448) ----
// enc Ws rows: 0..31 = Wih[k], 32..95 = Whh[k=0..63]  (96 rows * 2048B)
// dec Ws rows: 0..63 = Whh/Wsum[k=0..63]; fcW2 overlays at +131072
#define OFF_WS     0          // float Ws[96][Gv]            196608 B
#define OFF_FCW    131072     // ull fcW2[64][32] (dec only overlay) 16384 B
#define OFF_GACT   196608     // float gact[NB][Gv]           16384 B
#define OFF_HS8    212992     // float hs8[Hv][NB]             4096 B (batch-grouped h)
#define OFF_HSP    217088     // float hsp[NB][Hv]             4096 B
#define OFF_CS     221184     // float cs [NB][Hv]             4096 B
#define OFF_XS8    225280     // float xs8[Iv][NB]             1024 B
#define SMEM_BYTES 226304

// 8 batch-paired accumulators: a0..a3 = gate g0 x batchpairs, a4..a7 = gate g1
#define MAC8(PH, W0, W1)                                                  \
    {   ulonglong2 hA = *(const ulonglong2*)(PH);                         \
        ulonglong2 hB = *(const ulonglong2*)((const float*)(PH) + 4);     \
        ffma2(a0, hA.x, W0); ffma2(a1, hA.y, W0);                         \
        ffma2(a2, hB.x, W0); ffma2(a3, hB.y, W0);                         \
        ffma2(a4, hA.x, W1); ffma2(a5, hA.y, W1);                         \
        ffma2(a6, hB.x, W1); ffma2(a7, hB.y, W1); }

__global__ void __launch_bounds__(NT, 1) lstm_ae_kernel(
    const float* __restrict__ x,
    const float* __restrict__ eWih, const float* __restrict__ eWhh,
    const float* __restrict__ eBih, const float* __restrict__ eBhh,
    const float* __restrict__ dWih, const float* __restrict__ dWhh,
    const float* __restrict__ dBih, const float* __restrict__ dBhh,
    const float* __restrict__ fcW,  const float* __restrict__ fcB,
    float* __restrict__ out)
{
    extern __shared__ char smem[];
    float* Ws   = (float*)(smem + OFF_WS);
    ull*   fcW2 = (ull*)  (smem + OFF_FCW);
    float* gact = (float*)(smem + OFF_GACT);
    float* hs8  = (float*)(smem + OFF_HS8);
    float* hsp  = (float*)(smem + OFF_HSP);
    float* cs   = (float*)(smem + OFF_CS);
    float* xs8  = (float*)(smem + OFF_XS8);

    const int tid   = threadIdx.x;              // gate pair: gates 2*tid, 2*tid+1
    const int gt    = tid >> 6;                 // 0:i 1:f 2:g 3:o (warp-uniform)
    const int bbase = blockIdx.x * NB;
    float wra[KRv], wrb[KRv];                   // register weights (rows 64..127)

    // ======================= encoder setup =======================
    for (int idx = tid; idx < Gv * 96; idx += NT){
        int r = idx >> 9, g = idx & (Gv - 1);
        Ws[idx] = (r < 32) ? eWih[g * Iv + r] : eWhh[g * Hv + (r - 32)];
    }
    #pragma unroll
    for (int kk = 0; kk < KRv; kk++){
        wra[kk] = eWhh[(2*tid)     * Hv + KSe + kk];
        wrb[kk] = eWhh[(2*tid + 1) * Hv + KSe + kk];
    }
    ull bd0 = dup2(eBih[2*tid]     + eBhh[2*tid]);
    ull bd1 = dup2(eBih[2*tid + 1] + eBhh[2*tid + 1]);
    #pragma unroll
    for (int i = 0; i < 4; i++){ hs8[tid + i*NT] = 0.f; cs[tid + i*NT] = 0.f; }
    {   // x for t=0
        int row = tid & 31, b = tid >> 5;
        xs8[row * NB + b] = x[(size_t)(bbase + b) * Sv * Iv + row];
    }
    __syncthreads();

    const float* xbase = x + (size_t)(bbase + (tid >> 5)) * Sv * Iv + (tid & 31);
    const float* wp = Ws + 2*tid;

    // ======================= encoder loop =======================
    for (int t = 0; t < Sv; t++){
        // prefetch next x (hidden under MAC)
        int tn = (t + 1 < Sv) ? (t + 1) : t;
        float xnext = xbase[tn * Iv];

        ull a0 = bd0, a1 = bd0, a2 = bd0, a3 = bd0;
        ull a4 = bd1, a5 = bd1, a6 = bd1, a7 = bd1;

        #pragma unroll 8
        for (int r = 0; r < Iv; r++){
            float2 w = *(const float2*)(wp + r * Gv);
            MAC8(xs8 + r * NB, dup2(w.x), dup2(w.y));
        }
        #pragma unroll 8
        for (int k = 0; k < KSe; k++){
            float2 w = *(const float2*)(wp + (Iv + k) * Gv);
            MAC8(hs8 + k * NB, dup2(w.x), dup2(w.y));
        }
        #pragma unroll
        for (int kk = 0; kk < KRv; kk++){
            MAC8(hs8 + (KSe + kk) * NB, dup2(wra[kk]), dup2(wrb[kk]));
        }
        // activations -> gact[b][g]
        {
            float s0[8], s1[8];
            unpack2(a0, s0[0], s0[1]); unpack2(a1, s0[2], s0[3]);
            unpack2(a2, s0[4], s0[5]); unpack2(a3, s0[6], s0[7]);
            unpack2(a4, s1[0], s1[1]); unpack2(a5, s1[2], s1[3]);
            unpack2(a6, s1[4], s1[5]); unpack2(a7, s1[6], s1[7]);
            #pragma unroll
            for (int b = 0; b < NB; b++){
                float v0, v1;
                if (gt == 2){ v0 = tanh_(s0[b]); v1 = tanh_(s1[b]); }
                else        { v0 = sig_(s0[b]);  v1 = sig_(s1[b]);  }
                *(float2*)(gact + b * Gv + 2*tid) = make_float2(v0, v1);
            }
        }
        __syncthreads();                                  // B1: gact ready
        // c,h update: 4 items per thread; also store next x
        #pragma unroll
        for (int i = 0; i < 4; i++){
            int item = tid + i * NT;
            int b = item >> 7, u = item & (Hv - 1);
            const float* gb = gact + b * Gv;
            float iv = gb[u], fv = gb[Hv + u], gvv = gb[2*Hv + u], ov = gb[3*Hv + u];
            float cn = fv * cs[b * Hv + u] + iv * gvv;
            cs[b * Hv + u] = cn;
            hs8[u * NB + b] = ov * tanh_(cn);
        }
        xs8[(tid & 31) * NB + (tid >> 5)] = xnext;
        __syncthreads();                                  // B2: h/x ready
    }

    // ======================= decoder setup =======================
    // step 0 uses inp=0 => gates = h @ Whh^T only
    for (int idx = tid; idx < Gv * KSd; idx += NT){
        int r = idx >> 9, g = idx & (Gv - 1);
        Ws[idx] = dWhh[g * Hv + r];
    }
    #pragma unroll
    for (int kk = 0; kk < KRv; kk++){
        wra[kk] = dWhh[(2*tid)     * Hv + KSd + kk];
        wrb[kk] = dWhh[(2*tid + 1) * Hv + KSd + kk];
    }
    bd0 = dup2(dBih[2*tid]     + dBhh[2*tid]);
    bd1 = dup2(dBih[2*tid + 1] + dBhh[2*tid + 1]);
    for (int idx = tid; idx < 64 * 32; idx += NT){
        int o = idx & 31, k2 = idx >> 5;
        fcW2[idx] = pack2(fcW[o * Hv + 2*k2], fcW[o * Hv + 2*k2 + 1]);
    }
    const int fb = tid >> 5, fo = tid & 31;               // fc assignment (b, o)
    const float fcbv = fcB[fo];
    float* outbase = out + (size_t)(bbase + fb) * Sv * Iv + fo;
    // hs8 holds enc_h; cs holds enc_c (never modified in decoder)
    __syncthreads();

    // ======================= decoder loop =======================
    for (int t = 0; t < Sv; t++){
        ull a0 = bd0, a1 = bd0, a2 = bd0, a3 = bd0;
        ull a4 = bd1, a5 = bd1, a6 = bd1, a7 = bd1;

        #pragma unroll 8
        for (int k = 0; k < KSd; k++){
            float2 w = *(const float2*)(wp + k * Gv);
            MAC8(hs8 + k * NB, dup2(w.x), dup2(w.y));
        }
        #pragma unroll
        for (int kk = 0; kk < KRv; kk++){
            MAC8(hs8 + (KSd + kk) * NB, dup2(wra[kk]), dup2(wrb[kk]));
        }
        {
            float s0[8], s1[8];
            unpack2(a0, s0[0], s0[1]); unpack2(a1, s0[2], s0[3]);
            unpack2(a2, s0[4], s0[5]); unpack2(a3, s0[6], s0[7]);
            unpack2(a4, s1[0], s1[1]); unpack2(a5, s1[2], s1[3]);
            unpack2(a6, s1[4], s1[5]); unpack2(a7, s1[6], s1[7]);
            #pragma unroll
            for (int b = 0; b < NB; b++){
                float v0, v1;
                if (gt == 2){ v0 = tanh_(s0[b]); v1 = tanh_(s1[b]); }
                else        { v0 = sig_(s0[b]);  v1 = sig_(s1[b]);  }
                *(float2*)(gact + b * Gv + 2*tid) = make_float2(v0, v1);
            }
        }
        __syncthreads();                                  // B1: gact ready
        // h update: cell input is ALWAYS enc_c (cs), never written back
        #pragma unroll
        for (int i = 0; i < 4; i++){
            int item = tid + i * NT;
            int b = item >> 7, u = item & (Hv - 1);
            const float* gb = gact + b * Gv;
            float iv = gb[u], fv = gb[Hv + u], gvv = gb[2*Hv + u], ov = gb[3*Hv + u];
            float cn = fv * cs[b * Hv + u] + iv * gvv;
            float hn = ov * tanh_(cn);
            hs8[u * NB + b]  = hn;
            hsp[b * Hv + u]  = hn;
        }
        if (t == 0){
            // in place: Whh -> Whh + Wih (steps >=1 have inp == h)
            for (int idx = tid; idx < Gv * KSd; idx += NT){
                int r = idx >> 9, g = idx & (Gv - 1);
                Ws[idx] += dWih[g * Hv + r];
            }
            #pragma unroll
            for (int kk = 0; kk < KRv; kk++){
                wra[kk] += dWih[(2*tid)     * Hv + KSd + kk];
                wrb[kk] += dWih[(2*tid + 1) * Hv + KSd + kk];
            }
        }
        __syncthreads();                                  // B2: h/hsp/Ws ready
        // fc: frame = h_new @ fcW^T + fcb   (reads hsp; writes global only)
        {
            ull s = 0ull;
            const float* hb = hsp + fb * Hv;
            #pragma unroll 16
            for (int k2 = 0; k2 < Hv / 2; k2++){
                ull h2 = *(const ull*)(hb + 2*k2);
                ffma2(s, h2, fcW2[k2 * 32 + fo]);
            }
            float sa, sb; unpack2(s, sa, sb);
            outbase[t * Iv] = sa + sb + fcbv;
        }
        // fc reads complete before this thread passes next B1; hsp rewritten
        // only after next B1 -> safe
    }
}

extern "C" void kernel_launch(void* const* d_in, const int* in_sizes, int n_in,
                              void* d_out, int out_size)
{
    const float* x    = (const float*)d_in[0];
    const float* eWih = (const float*)d_in[1];
    const float* eWhh = (const float*)d_in[2];
    const float* eBih = (const float*)d_in[3];
    const float* eBhh = (const float*)d_in[4];
    const float* dWih = (const float*)d_in[5];
    const float* dWhh = (const float*)d_in[6];
    const float* dBih = (const float*)d_in[7];
    const float* dBhh = (const float*)d_in[8];
    const float* fcW  = (const float*)d_in[9];
    const float* fcB  = (const float*)d_in[10];
    float* out = (float*)d_out;

    cudaFuncSetAttribute(lstm_ae_kernel,
                         cudaFuncAttributeMaxDynamicSharedMemorySize, SMEM_BYTES);
    lstm_ae_kernel<<<NCTA, NT, SMEM_BYTES>>>(
        x, eWih, eWhh, eBih, eBhh, dWih, dWhh, dBih, dBhh, fcW, fcB, out);
}

// round 7
// speedup vs baseline: 1.6744x; 1.6744x over previous
#include <cuda_runtime.h>

#define Sv    512
#define Iv    32
#define Hv    128
#define Gv    512      // 4*H
#define NB    4        // batches per CTA
#define NT    256      // threads per CTA (one gate-pair per thread)
#define NCTA  128      // 128 * 4 = 512 batches
#define KS    64       // weight rows (k) in shared memory
#define KR    64       // weight rows (k) in registers

typedef unsigned long long ull;

// ---- device scratch (static allocation is allowed; no cudaMalloc) ----
__device__ float4 g_xg[(size_t)Sv * NCTA * Gv];   // [t][cta][g] -> {b0,b1,b2,b3} (x@Wih^T + bias)
__device__ float  g_hall[(size_t)Sv * 512 * Hv];  // [t][b][u]  decoder hidden states

static __device__ __forceinline__ ull pack2(float a, float b){
    ull r; asm("mov.b64 %0, {%1,%2};" : "=l"(r) : "f"(a), "f"(b)); return r;
}
static __device__ __forceinline__ ull dup2(float a){
    ull r; asm("mov.b64 %0, {%1,%1};" : "=l"(r) : "f"(a)); return r;
}
static __device__ __forceinline__ void unpack2(ull v, float& a, float& b){
    asm("mov.b64 {%0,%1}, %2;" : "=f"(a), "=f"(b) : "l"(v));
}
// Blackwell packed fp32x2 FMA: d = a*b + d (two independent fp32 lanes)
static __device__ __forceinline__ void ffma2(ull& d, ull a, ull b){
    asm("fma.rn.f32x2 %0, %1, %2, %0;" : "+l"(d) : "l"(a), "l"(b));
}
static __device__ __forceinline__ float sig_(float x){
    return __fdividef(1.f, 1.f + __expf(-x));
}
static __device__ __forceinline__ float tanh_(float x){
    float ax = fabsf(x);
    float t  = __expf(-2.f * ax);
    float r  = __fdividef(1.f - t, 1.f + t);
    return copysignf(r, x);
}

// =====================================================================
// Kernel 1: encoder x-projection  g_xg[t][cta][g][b] = x[b,t,:]@Wih^T + bias
// grid = 512 (128 ctas x 4 time-quarters), block = 256
// =====================================================================
__global__ void __launch_bounds__(256, 1) xproj_kernel(
    const float* __restrict__ x, const float* __restrict__ Wih,
    const float* __restrict__ bih, const float* __restrict__ bhh)
{
    __shared__ float xs[Iv * NB];
    const int tid = threadIdx.x;
    const int c   = blockIdx.x & (NCTA - 1);
    const int tq  = blockIdx.x >> 7;
    const int bbase = c * NB;

    float wA[Iv], wB[Iv];
    #pragma unroll
    for (int k = 0; k < Iv; k++){
        wA[k] = Wih[(2*tid)     * Iv + k];
        wB[k] = Wih[(2*tid + 1) * Iv + k];
    }
    const ull bd0 = dup2(bih[2*tid]     + bhh[2*tid]);
    const ull bd1 = dup2(bih[2*tid + 1] + bhh[2*tid + 1]);

    for (int tt = 0; tt < Sv/4; tt++){
        int t = tq * (Sv/4) + tt;
        if (tid < Iv * NB){
            int i = tid & 31, bb = tid >> 5;
            xs[i * NB + bb] = x[((size_t)(bbase + bb) * Sv + t) * Iv + i];
        }
        __syncthreads();
        ull a0 = bd0, a1 = bd0, a2 = bd1, a3 = bd1;
        #pragma unroll
        for (int k = 0; k < Iv; k++){
            ulonglong2 h = *(const ulonglong2*)(xs + k * NB);
            ull w0 = dup2(wA[k]), w1 = dup2(wB[k]);
            ffma2(a0, h.x, w0); ffma2(a1, h.y, w0);
            ffma2(a2, h.x, w1); ffma2(a3, h.y, w1);
        }
        float4 o0, o1;
        unpack2(a0, o0.x, o0.y); unpack2(a1, o0.z, o0.w);
        unpack2(a2, o1.x, o1.y); unpack2(a3, o1.z, o1.w);
        size_t base = ((size_t)t * NCTA + c) * Gv + 2*tid;
        g_xg[base]     = o0;
        g_xg[base + 1] = o1;
        __syncthreads();
    }
}

// =====================================================================
// Kernel 2: persistent recurrence (encoder + decoder), 128 CTAs x 256
// =====================================================================
#define OFF_WS    0                      // float Ws[KS][Gv]   131072 B
#define OFF_GACT  131072                 // float gact[NB][Gv]   8192 B
#define OFF_HS4   139264                 // float hs4[Hv][NB]    2048 B
#define SMEM_BYTES 141312

#define MACB(PH, W0, W1)                                                  \
    {   ulonglong2 h = *(const ulonglong2*)(PH);                          \
        ffma2(a0, h.x, W0); ffma2(a1, h.y, W0);                           \
        ffma2(a2, h.x, W1); ffma2(a3, h.y, W1); }

__global__ void __launch_bounds__(NT, 1) lstm_ae_kernel(
    const float* __restrict__ eWhh,
    const float* __restrict__ dWih, const float* __restrict__ dWhh,
    const float* __restrict__ dBih, const float* __restrict__ dBhh)
{
    extern __shared__ char smem[];
    float* Ws   = (float*)(smem + OFF_WS);
    float* gact = (float*)(smem + OFF_GACT);
    float* hs4  = (float*)(smem + OFF_HS4);

    const int tid   = threadIdx.x;           // gate pair 2*tid, 2*tid+1
    const int gt    = tid >> 6;              // 0:i 1:f 2:g 3:o
    const int cta   = blockIdx.x;
    const int bbase = cta * NB;
    const int u     = tid & (Hv - 1);        // epilogue unit
    const int b0    = tid >> 7;              // epilogue batches b0, b0+2
    float wra[KR], wrb[KR];
    float c0 = 0.f, c1 = 0.f;                // cell state in registers

    // ---------------- encoder setup ----------------
    for (int idx = tid; idx < Gv * KS; idx += NT){
        int r = idx >> 9, g = idx & (Gv - 1);
        Ws[idx] = eWhh[g * Hv + r];
    }
    #pragma unroll
    for (int kk = 0; kk < KR; kk++){
        wra[kk] = eWhh[(2*tid)     * Hv + KS + kk];
        wrb[kk] = eWhh[(2*tid + 1) * Hv + KS + kk];
    }
    hs4[tid] = 0.f; hs4[tid + NT] = 0.f;
    // preload x-gates for t=0
    float4 xc0, xc1;
    {   size_t p = (size_t)cta * Gv + 2*tid;
        xc0 = g_xg[p]; xc1 = g_xg[p + 1]; }
    __syncthreads();

    const float* wp = Ws + 2*tid;
    const float* gA = gact + b0 * Gv;
    const float* gB = gact + (b0 + 2) * Gv;

    // ---------------- encoder loop ----------------
    for (int t = 0; t < Sv; t++){
        float4 xn0 = xc0, xn1 = xc1;
        if (t + 1 < Sv){
            size_t p = ((size_t)(t + 1) * NCTA + cta) * Gv + 2*tid;
            xn0 = g_xg[p]; xn1 = g_xg[p + 1];
        }
        ull a0 = pack2(xc0.x, xc0.y), a1 = pack2(xc0.z, xc0.w);
        ull a2 = pack2(xc1.x, xc1.y), a3 = pack2(xc1.z, xc1.w);

        #pragma unroll 8
        for (int k = 0; k < KS; k++){
            float2 w = *(const float2*)(wp + k * Gv);
            MACB(hs4 + k * NB, dup2(w.x), dup2(w.y));
        }
        #pragma unroll
        for (int kk = 0; kk < KR; kk++){
            MACB(hs4 + (KS + kk) * NB, dup2(wra[kk]), dup2(wrb[kk]));
        }
        {   // activations -> gact
            float s0[4], s1[4];
            unpack2(a0, s0[0], s0[1]); unpack2(a1, s0[2], s0[3]);
            unpack2(a2, s1[0], s1[1]); unpack2(a3, s1[2], s1[3]);
            #pragma unroll
            for (int b = 0; b < NB; b++){
                float v0, v1;
                if (gt == 2){ v0 = tanh_(s0[b]); v1 = tanh_(s1[b]); }
                else        { v0 = sig_(s0[b]);  v1 = sig_(s1[b]);  }
                *(float2*)(gact + b * Gv + 2*tid) = make_float2(v0, v1);
            }
        }
        __syncthreads();                               // B1: gact ready
        {   // c,h update: c lives in registers
            float i0 = gA[u], f0 = gA[Hv+u], g0v = gA[2*Hv+u], o0v = gA[3*Hv+u];
            float i1 = gB[u], f1 = gB[Hv+u], g1v = gB[2*Hv+u], o1v = gB[3*Hv+u];
            c0 = f0 * c0 + i0 * g0v;
            c1 = f1 * c1 + i1 * g1v;
            hs4[u * NB + b0]     = o0v * tanh_(c0);
            hs4[u * NB + b0 + 2] = o1v * tanh_(c1);
        }
        xc0 = xn0; xc1 = xn1;
        __syncthreads();                               // B2: h ready
    }
    // c0,c1 now hold enc_c (read-only in decoder); hs4 holds enc_h

    // ---------------- decoder setup ----------------
    for (int idx = tid; idx < Gv * KS; idx += NT){
        int r = idx >> 9, g = idx & (Gv - 1);
        Ws[idx] = dWhh[g * Hv + r];
    }
    #pragma unroll
    for (int kk = 0; kk < KR; kk++){
        wra[kk] = dWhh[(2*tid)     * Hv + KS + kk];
        wrb[kk] = dWhh[(2*tid + 1) * Hv + KS + kk];
    }
    const ull bd0 = dup2(dBih[2*tid]     + dBhh[2*tid]);
    const ull bd1 = dup2(dBih[2*tid + 1] + dBhh[2*tid + 1]);
    float* hallp0 = g_hall + (size_t)(bbase + b0)     * Hv + u;  // + t*512*Hv
    float* hallp1 = g_hall + (size_t)(bbase + b0 + 2) * Hv + u;
    __syncthreads();

    // ---------------- decoder loop ----------------
    for (int t = 0; t < Sv; t++){
        ull a0 = bd0, a1 = bd0, a2 = bd1, a3 = bd1;

        #pragma unroll 8
        for (int k = 0; k < KS; k++){
            float2 w = *(const float2*)(wp + k * Gv);
            MACB(hs4 + k * NB, dup2(w.x), dup2(w.y));
        }
        #pragma unroll
        for (int kk = 0; kk < KR; kk++){
            MACB(hs4 + (KS + kk) * NB, dup2(wra[kk]), dup2(wrb[kk]));
        }
        {
            float s0[4], s1[4];
            unpack2(a0, s0[0], s0[1]); unpack2(a1, s0[2], s0[3]);
            unpack2(a2, s1[0], s1[1]); unpack2(a3, s1[2], s1[3]);
            #pragma unroll
            for (int b = 0; b < NB; b++){
                float v0, v1;
                if (gt == 2){ v0 = tanh_(s0[b]); v1 = tanh_(s1[b]); }
                else        { v0 = sig_(s0[b]);  v1 = sig_(s1[b]);  }
                *(float2*)(gact + b * Gv + 2*tid) = make_float2(v0, v1);
            }
        }
        __syncthreads();                               // B1: gact ready
        {   // h update: cell input is ALWAYS enc_c (c0,c1 regs, read-only)
            float i0 = gA[u], f0 = gA[Hv+u], g0v = gA[2*Hv+u], o0v = gA[3*Hv+u];
            float i1 = gB[u], f1 = gB[Hv+u], g1v = gB[2*Hv+u], o1v = gB[3*Hv+u];
            float cn0 = f0 * c0 + i0 * g0v;
            float cn1 = f1 * c1 + i1 * g1v;
            float h0 = o0v * tanh_(cn0);
            float h1 = o1v * tanh_(cn1);
            hs4[u * NB + b0]     = h0;
            hs4[u * NB + b0 + 2] = h1;
            size_t toff = (size_t)t * 512 * Hv;
            hallp0[toff] = h0;                         // fc deferred to kernel 3
            hallp1[toff] = h1;
        }
        if (t == 0){
            // in place: Whh -> Whh + Wih (steps >=1 have inp == h)
            for (int idx = tid; idx < Gv * KS; idx += NT){
                int r = idx >> 9, g = idx & (Gv - 1);
                Ws[idx] += dWih[g * Hv + r];
            }
            #pragma unroll
            for (int kk = 0; kk < KR; kk++){
                wra[kk] += dWih[(2*tid)     * Hv + KS + kk];
                wrb[kk] += dWih[(2*tid + 1) * Hv + KS + kk];
            }
        }
        __syncthreads();                               // B2: h/Ws ready
    }
}

// =====================================================================
// Kernel 3: deferred fc  out[b,t,:] = g_hall[t,b,:]@fcW^T + fcB
// grid = 4096 (64 rows each), block = 256
// =====================================================================
__global__ void __launch_bounds__(256, 1) fc_kernel(
    const float* __restrict__ fcW, const float* __restrict__ fcB,
    float* __restrict__ out)
{
    __shared__ ull   wsm[64 * 32];      // 16 KB packed fcW pairs
    __shared__ float hsm[64 * Hv];      // 32 KB staged h rows
    const int tid = threadIdx.x;

    for (int idx = tid; idx < 2048; idx += 256){
        int o = idx & 31, k2 = idx >> 5;
        wsm[idx] = pack2(fcW[o * Hv + 2*k2], fcW[o * Hv + 2*k2 + 1]);
    }
    const size_t rbase = (size_t)blockIdx.x * 64;      // row r = t*512 + b
    {   const float4* hg = (const float4*)(g_hall + rbase * Hv);
        float4* hd = (float4*)hsm;
        #pragma unroll
        for (int i = 0; i < 8; i++) hd[tid + i * 256] = hg[tid + i * 256];
    }
    __syncthreads();

    const int o = tid & 31, wq = tid >> 5;
    const float fb = fcB[o];
    #pragma unroll
    for (int i = 0; i < 8; i++){
        int rloc = wq * 8 + i;
        const float* hr = hsm + rloc * Hv;
        ull s = 0ull;
        #pragma unroll 16
        for (int k2 = 0; k2 < Hv/2; k2++){
            ull h2 = *(const ull*)(hr + 2*k2);
            ffma2(s, h2, wsm[k2 * 32 + o]);
        }
        float sa, sb; unpack2(s, sa, sb);
        size_t r = rbase + rloc;
        size_t b = r & 511, t = r >> 9;
        out[(b * Sv + t) * Iv + o] = sa + sb + fb;
    }
}

extern "C" void kernel_launch(void* const* d_in, const int* in_sizes, int n_in,
                              void* d_out, int out_size)
{
    const float* x    = (const float*)d_in[0];
    const float* eWih = (const float*)d_in[1];
    const float* eWhh = (const float*)d_in[2];
    const float* eBih = (const float*)d_in[3];
    const float* eBhh = (const float*)d_in[4];
    const float* dWih = (const float*)d_in[5];
    const float* dWhh = (const float*)d_in[6];
    const float* dBih = (const float*)d_in[7];
    const float* dBhh = (const float*)d_in[8];
    const float* fcW  = (const float*)d_in[9];
    const float* fcB  = (const float*)d_in[10];
    float* out = (float*)d_out;

    cudaFuncSetAttribute(lstm_ae_kernel,
                         cudaFuncAttributeMaxDynamicSharedMemorySize, SMEM_BYTES);
    xproj_kernel<<<512, 256>>>(x, eWih, eBih, eBhh);
    lstm_ae_kernel<<<NCTA, NT, SMEM_BYTES>>>(eWhh, dWih, dWhh, dBih, dBhh);
    fc_kernel<<<4096, 256>>>(fcW, fcB, out);
}